// round 2
// baseline (speedup 1.0000x reference)
#include <cuda_runtime.h>
#include <cuda_fp16.h>
#include <math.h>
#include <stdint.h>

#define BB 256
#define KK 8
#define NN 512
#define OO 64
#define EE 64
#define L2E 1.4426950408889634f

// pass-kernel grid split
#define SPL 16
#define CHUNK (NN / SPL)   // 32 n-rows per CTA

// ---------------- global scratch (static device memory: allowed) ----------------
__device__ __half g_w0[(size_t)BB * KK * NN * OO];  // 134 MB  u0 = 2^8 exp(cc - max_k cc)
__device__ __half g_p [(size_t)BB * NN * OO];       // 16.8 MB priors fp16
__device__ float  g_d [BB * KK * NN];               // 4 MB    routing logit deltas
__device__ float  g_z [BB * KK * OO];               // 512 KB  (zero at load; kept zero by our kernels)
__device__ float  g_v [BB * KK * OO];               // 512 KB

__device__ __forceinline__ float ex2(float x) {
    float r;
    asm("ex2.approx.ftz.f32 %0, %1;" : "=f"(r) : "f"(x));
    return r;
}

// ---------------- KA: priors p = emb @ S  (fp32 compute, fp16 store) ----------------
__global__ __launch_bounds__(256, 4)
void ka_priors(const float* __restrict__ emb, const float* __restrict__ S) {
    __shared__ float Ssh[EE * OO];
    const int b     = blockIdx.x >> 1;
    const int half  = blockIdx.x & 1;
    const int tid   = threadIdx.x;
    const int warp  = tid >> 5;
    const int lane  = tid & 31;
    const int nbase = half * 256;

    for (int i = tid; i < EE * OO; i += 256) Ssh[i] = S[i];
    __syncthreads();

    const int o2 = lane * 2;
    const float* embb = emb + (size_t)b * (NN * EE);
    __half* pb = g_p + (size_t)b * NN * OO;

    #pragma unroll 1
    for (int gi = 0; gi < 8; gi++) {
        const int n0 = nbase + warp * 32 + gi * 4;
        const float4* r0 = (const float4*)(embb + (size_t)(n0 + 0) * EE);
        const float4* r1 = (const float4*)(embb + (size_t)(n0 + 1) * EE);
        const float4* r2 = (const float4*)(embb + (size_t)(n0 + 2) * EE);
        const float4* r3 = (const float4*)(embb + (size_t)(n0 + 3) * EE);
        float2 a0 = make_float2(0.f, 0.f), a1 = a0, a2 = a0, a3 = a0;
        #pragma unroll
        for (int e4 = 0; e4 < EE / 4; e4++) {
            float4 x0 = r0[e4], x1 = r1[e4], x2 = r2[e4], x3 = r3[e4];
            const float* sb = &Ssh[e4 * 4 * OO + o2];
            float2 s0 = *(const float2*)(sb);
            float2 s1 = *(const float2*)(sb + OO);
            float2 s2 = *(const float2*)(sb + 2 * OO);
            float2 s3 = *(const float2*)(sb + 3 * OO);
            a0.x += x0.x*s0.x + x0.y*s1.x + x0.z*s2.x + x0.w*s3.x;
            a0.y += x0.x*s0.y + x0.y*s1.y + x0.z*s2.y + x0.w*s3.y;
            a1.x += x1.x*s0.x + x1.y*s1.x + x1.z*s2.x + x1.w*s3.x;
            a1.y += x1.x*s0.y + x1.y*s1.y + x1.z*s2.y + x1.w*s3.y;
            a2.x += x2.x*s0.x + x2.y*s1.x + x2.z*s2.x + x2.w*s3.x;
            a2.y += x2.x*s0.y + x2.y*s1.y + x2.z*s2.y + x2.w*s3.y;
            a3.x += x3.x*s0.x + x3.y*s1.x + x3.z*s2.x + x3.w*s3.x;
            a3.y += x3.x*s0.y + x3.y*s1.y + x3.z*s2.y + x3.w*s3.y;
        }
        *(__half2*)(pb + (size_t)(n0 + 0) * OO + o2) = __floats2half2_rn(a0.x, a0.y);
        *(__half2*)(pb + (size_t)(n0 + 1) * OO + o2) = __floats2half2_rn(a1.x, a1.y);
        *(__half2*)(pb + (size_t)(n0 + 2) * OO + o2) = __floats2half2_rn(a2.x, a2.y);
        *(__half2*)(pb + (size_t)(n0 + 3) * OO + o2) = __floats2half2_rn(a3.x, a3.y);
    }
}

// ---------------- z reduce helper (shared -> global) ----------------
__device__ __forceinline__ void z_reduce(float* zsm, const float za[16], int b, int lane, int tid) {
    const int o2 = lane * 2;
    #pragma unroll
    for (int k = 0; k < KK; k++) {
        atomicAdd(&zsm[k * 66 + o2],     za[2 * k]);
        atomicAdd(&zsm[k * 66 + o2 + 1], za[2 * k + 1]);
    }
    __syncthreads();
    for (int i = tid; i < KK * OO; i += 256) {
        int k = i >> 6, o = i & 63;
        atomicAdd(&g_z[b * (KK * OO) + i], zsm[k * 66 + o]);
    }
}

// ---------------- KB1: pass 1 (reads fp32 cc, writes fp16 u0, accumulates z) ----------------
__global__ __launch_bounds__(256, 5)
void kb_pass1(const float* __restrict__ cc) {
    __shared__ float zsm[KK * 66];
    const int b     = blockIdx.x / SPL;
    const int nbase = (blockIdx.x % SPL) * CHUNK;
    const int tid   = threadIdx.x;
    const int warp  = tid >> 5;
    const int lane  = tid & 31;
    const int o2    = lane * 2;

    for (int i = tid; i < KK * 66; i += 256) zsm[i] = 0.0f;
    __syncthreads();

    float za[16];
    #pragma unroll
    for (int i = 0; i < 16; i++) za[i] = 0.0f;

    const size_t rowb = (size_t)b * KK * NN;   // element-row base (k=0)

    #pragma unroll 1
    for (int i = 0; i < CHUNK / 8; i++) {      // 8 warps * 4 n each
        const int n = nbase + warp * (CHUNK / 8) + i;
        const size_t eb = (rowb + n) * OO + o2;
        const float2* cp = (const float2*)(cc + eb);
        __half2* wp = (__half2*)(g_w0 + eb);
        float2 c[KK];
        #pragma unroll
        for (int k = 0; k < KK; k++) c[k] = cp[k * (NN * OO / 2)];
        float mx = c[0].x, my = c[0].y;
        #pragma unroll
        for (int k = 1; k < KK; k++) { mx = fmaxf(mx, c[k].x); my = fmaxf(my, c[k].y); }
        const float ax = 8.0f - mx * L2E, ay = 8.0f - my * L2E;
        float dx = 0.0f, dy = 0.0f;
        #pragma unroll
        for (int k = 0; k < KK; k++) {
            float ex_ = ex2(fmaf(c[k].x, L2E, ax));
            float ey_ = ex2(fmaf(c[k].y, L2E, ay));
            wp[k * (NN * OO / 2)] = __floats2half2_rn(ex_, ey_);
            dx += ex_; dy += ey_;
            c[k].x = ex_; c[k].y = ey_;
        }
        float2 pf = __half22float2(*(const __half2*)(g_p + ((size_t)b * NN + n) * OO + o2));
        float wx = __fdividef(pf.x, dx), wy = __fdividef(pf.y, dy);
        #pragma unroll
        for (int k = 0; k < KK; k++) {
            za[2 * k]     = fmaf(c[k].x, wx, za[2 * k]);
            za[2 * k + 1] = fmaf(c[k].y, wy, za[2 * k + 1]);
        }
    }
    z_reduce(zsm, za, b, lane, tid);
}

// ---------------- KB2: passes 2/3 (reads fp16 u0 + d, accumulates z) ----------------
__global__ __launch_bounds__(256, 5)
void kb_pass_next(int dummy) {
    __shared__ float zsm[KK * 66];
    __shared__ float ed[KK][CHUNK];
    __shared__ float dmv[CHUNK];
    const int b     = blockIdx.x / SPL;
    const int nbase = (blockIdx.x % SPL) * CHUNK;
    const int tid   = threadIdx.x;
    const int warp  = tid >> 5;
    const int lane  = tid & 31;
    const int o2    = lane * 2;

    const float* dbase = g_d + (size_t)b * KK * NN + nbase;
    for (int i = tid; i < KK * 66; i += 256) zsm[i] = 0.0f;
    if (tid < CHUNK) {
        float m = dbase[tid];
        #pragma unroll
        for (int k = 1; k < KK; k++) m = fmaxf(m, dbase[k * NN + tid]);
        dmv[tid] = m;
    }
    __syncthreads();
    {   // KK*CHUNK = 256 entries, one per thread
        int k = tid >> 5, nl = tid & (CHUNK - 1);
        ed[k][nl] = ex2((dbase[k * NN + nl] - dmv[nl]) * L2E);
    }
    __syncthreads();

    float za[16];
    #pragma unroll
    for (int i = 0; i < 16; i++) za[i] = 0.0f;

    const size_t rowb = (size_t)b * KK * NN;

    #pragma unroll 1
    for (int i = 0; i < CHUNK / 8; i++) {
        const int nl = warp * (CHUNK / 8) + i;
        const int n  = nbase + nl;
        const __half2* wp = (const __half2*)(g_w0 + (rowb + n) * OO + o2);
        float ex_[KK], ey_[KK];
        float dx = 0.0f, dy = 0.0f;
        #pragma unroll
        for (int k = 0; k < KK; k++) {
            float2 u = __half22float2(wp[k * (NN * OO / 2)]);
            float e = ed[k][nl];
            ex_[k] = u.x * e; ey_[k] = u.y * e;
            dx += ex_[k]; dy += ey_[k];
        }
        float2 pf = __half22float2(*(const __half2*)(g_p + ((size_t)b * NN + n) * OO + o2));
        float wx = __fdividef(pf.x, dx), wy = __fdividef(pf.y, dy);
        #pragma unroll
        for (int k = 0; k < KK; k++) {
            za[2 * k]     = fmaf(ex_[k], wx, za[2 * k]);
            za[2 * k + 1] = fmaf(ey_[k], wy, za[2 * k + 1]);
        }
    }
    z_reduce(zsm, za, b, lane, tid);
}

// ---------------- KC0: v = squash(z); z = 0 ----------------
__global__ void kc0_squash(int dummy) {
    const int b    = blockIdx.x;
    const int warp = threadIdx.x >> 5;  // = k
    const int lane = threadIdx.x & 31;
    const int base = b * (KK * OO) + warp * OO;
    float z0 = g_z[base + lane], z1 = g_z[base + lane + 32];
    float sq = z0 * z0 + z1 * z1;
    #pragma unroll
    for (int off = 16; off > 0; off >>= 1) sq += __shfl_xor_sync(0xffffffffu, sq, off);
    float c = sq / ((1.0f + sq) * sqrtf(sq + 1e-9f));
    g_v[base + lane]      = c * z0;
    g_v[base + lane + 32] = c * z1;
    g_z[base + lane]      = 0.0f;
    g_z[base + lane + 32] = 0.0f;
}

// ---------------- KC1: d (=|+=) p . v ----------------
template <bool FIRSTI>
__global__ __launch_bounds__(256, 4)
void kc1_sim(int dummy) {
    __shared__ __half2 psm[256 * 33];
    __shared__ float   vsm[KK * OO];
    const int b   = blockIdx.x >> 1;
    const int nb  = (blockIdx.x & 1) * 256;
    const int tid = threadIdx.x;

    const __half2* pg = (const __half2*)(g_p + ((size_t)b * NN + nb) * OO);
    for (int i = tid; i < 256 * 32; i += 256) {
        int row = i >> 5, c2 = i & 31;
        psm[row * 33 + c2] = pg[row * 32 + c2];
    }
    for (int i = tid; i < KK * OO; i += 256) vsm[i] = g_v[b * (KK * OO) + i];
    __syncthreads();

    float acc[KK];
    #pragma unroll
    for (int k = 0; k < KK; k++) acc[k] = 0.0f;
    const float2* v2 = (const float2*)vsm;
    #pragma unroll 4
    for (int o2i = 0; o2i < 32; o2i++) {
        float2 pf = __half22float2(psm[tid * 33 + o2i]);
        #pragma unroll
        for (int k = 0; k < KK; k++) {
            float2 vv = v2[k * 32 + o2i];
            acc[k] = fmaf(pf.x, vv.x, fmaf(pf.y, vv.y, acc[k]));
        }
    }
    const int n = nb + tid;
    #pragma unroll
    for (int k = 0; k < KK; k++) {
        size_t di = ((size_t)b * KK + k) * NN + n;
        if (FIRSTI) g_d[di] = acc[k];
        else        g_d[di] += acc[k];
    }
}

// ---------------- KD: out = squash(z); z = 0 ----------------
__global__ void kd_out(float* __restrict__ out) {
    const int b    = blockIdx.x;
    const int warp = threadIdx.x >> 5;
    const int lane = threadIdx.x & 31;
    const int base = b * (KK * OO) + warp * OO;
    float z0 = g_z[base + lane], z1 = g_z[base + lane + 32];
    float sq = z0 * z0 + z1 * z1;
    #pragma unroll
    for (int off = 16; off > 0; off >>= 1) sq += __shfl_xor_sync(0xffffffffu, sq, off);
    float c = sq / ((1.0f + sq) * sqrtf(sq + 1e-9f));
    out[base + lane]      = c * z0;
    out[base + lane + 32] = c * z1;
    g_z[base + lane]      = 0.0f;
    g_z[base + lane + 32] = 0.0f;
}

// ---------------- host ----------------
extern "C" void kernel_launch(void* const* d_in, const int* in_sizes, int n_in,
                              void* d_out, int out_size)
{
    const float* emb = nullptr;
    const float* S   = nullptr;
    const float* cc  = nullptr;
    for (int i = 0; i < n_in; i++) {
        if (in_sizes[i] == BB * NN * EE)           emb = (const float*)d_in[i];
        else if (in_sizes[i] == EE * OO)           S   = (const float*)d_in[i];
        else if (in_sizes[i] == BB * KK * NN * OO) cc  = (const float*)d_in[i];
    }
    float* out = (float*)d_out;

    ka_priors<<<BB * 2, 256>>>(emb, S);
    kb_pass1<<<BB * SPL, 256>>>(cc);
    kc0_squash<<<BB, 256>>>(0);
    kc1_sim<true><<<BB * 2, 256>>>(0);
    kb_pass_next<<<BB * SPL, 256>>>(0);
    kc0_squash<<<BB, 256>>>(0);
    kc1_sim<false><<<BB * 2, 256>>>(0);
    kb_pass_next<<<BB * SPL, 256>>>(0);
    kd_out<<<BB, 256>>>(out);
}

// round 3
// speedup vs baseline: 1.6821x; 1.6821x over previous
#include <cuda_runtime.h>
#include <cuda_fp16.h>
#include <math.h>
#include <stdint.h>

// DynamicRoutingLayer fused: B=256, N=512, E=64, O=64, K=8, 3 passes.
// One CTA per batch, 512 threads, 2 CTAs/SM (fp16 priors in shared).
// cc streamed from HBM 3x; routing delta d[k][n] lives in shared.

#define BB 256
#define NN 512
#define EE 64
#define OO 64
#define KK 8
#define THREADS 512
#define L2E 1.4426950408889634f

// shared layout (float units). psm is half2[512][33] = 16896 floats.
#define P_FLOATS 16896
#define D_OFF   P_FLOATS                 // d[K][512]
#define T_OFF   (D_OFF + KK * NN)        // tk[K][512]  (== Ssh during phase A)
#define Z_OFF   (T_OFF + KK * NN)        // z[K][66]
#define V_OFF   (Z_OFF + KK * 66)        // v[K][66]
#define DM_OFF  (V_OFF + KK * 66)        // dm[512]
#define SMEM_FLOATS (DM_OFF + NN)
#define SMEM_BYTES  (SMEM_FLOATS * 4)    // 106624 B

__device__ __forceinline__ float ex2(float x) {
    float r;
    asm("ex2.approx.ftz.f32 %0, %1;" : "=f"(r) : "f"(x));
    return r;
}

__global__ __launch_bounds__(THREADS, 2)
void routing_kernel(const float* __restrict__ emb,
                    const float* __restrict__ S,
                    const float* __restrict__ cc,
                    float* __restrict__ out)
{
    extern __shared__ float sm[];
    __half2* psm = (__half2*)sm;          // [n][33] half2, stride 33
    float* dsm  = sm + D_OFF;
    float* tsm  = sm + T_OFF;             // Ssh during phase A
    float* zsm  = sm + Z_OFF;
    float* vsm  = sm + V_OFF;
    float* dmsm = sm + DM_OFF;

    const int b    = blockIdx.x;
    const int tid  = threadIdx.x;
    const int warp = tid >> 5;
    const int lane = tid & 31;
    const int o2   = lane * 2;

    // ---- init: zero d, load S into tsm ----
    #pragma unroll
    for (int i = 0; i < KK * NN / THREADS; i++) dsm[tid + i * THREADS] = 0.0f;
    float* Ssh = tsm;
    #pragma unroll
    for (int i = 0; i < EE * OO / THREADS; i++) Ssh[tid + i * THREADS] = S[tid + i * THREADS];
    __syncthreads();

    // ---- Phase A: priors p[n][o] = emb[b,n,:] @ S[:,o], stored fp16 ----
    {
        const float* embb = emb + (size_t)b * (NN * EE);
        #pragma unroll 1
        for (int gi = 0; gi < 8; gi++) {
            const int n0 = warp * 32 + gi * 4;
            const float4* r0 = (const float4*)(embb + (size_t)(n0 + 0) * EE);
            const float4* r1 = (const float4*)(embb + (size_t)(n0 + 1) * EE);
            const float4* r2 = (const float4*)(embb + (size_t)(n0 + 2) * EE);
            const float4* r3 = (const float4*)(embb + (size_t)(n0 + 3) * EE);
            float2 a0 = make_float2(0.f, 0.f), a1 = a0, a2 = a0, a3 = a0;
            #pragma unroll
            for (int e4 = 0; e4 < EE / 4; e4++) {
                float4 x0 = r0[e4], x1 = r1[e4], x2 = r2[e4], x3 = r3[e4];
                const float* sb = &Ssh[e4 * 4 * OO + o2];
                float2 s0 = *(const float2*)(sb);
                float2 s1 = *(const float2*)(sb + OO);
                float2 s2 = *(const float2*)(sb + 2 * OO);
                float2 s3 = *(const float2*)(sb + 3 * OO);
                a0.x += x0.x*s0.x + x0.y*s1.x + x0.z*s2.x + x0.w*s3.x;
                a0.y += x0.x*s0.y + x0.y*s1.y + x0.z*s2.y + x0.w*s3.y;
                a1.x += x1.x*s0.x + x1.y*s1.x + x1.z*s2.x + x1.w*s3.x;
                a1.y += x1.x*s0.y + x1.y*s1.y + x1.z*s2.y + x1.w*s3.y;
                a2.x += x2.x*s0.x + x2.y*s1.x + x2.z*s2.x + x2.w*s3.x;
                a2.y += x2.x*s0.y + x2.y*s1.y + x2.z*s2.y + x2.w*s3.y;
                a3.x += x3.x*s0.x + x3.y*s1.x + x3.z*s2.x + x3.w*s3.x;
                a3.y += x3.x*s0.y + x3.y*s1.y + x3.z*s2.y + x3.w*s3.y;
            }
            psm[(n0 + 0) * 33 + lane] = __floats2half2_rn(a0.x, a0.y);
            psm[(n0 + 1) * 33 + lane] = __floats2half2_rn(a1.x, a1.y);
            psm[(n0 + 2) * 33 + lane] = __floats2half2_rn(a2.x, a2.y);
            psm[(n0 + 3) * 33 + lane] = __floats2half2_rn(a3.x, a3.y);
        }
    }
    __syncthreads();

    // ---- Phase B: 3 passes ----
    const size_t ccb = (size_t)b * (KK * NN * OO);

    #pragma unroll 1
    for (int t = 0; t < 3; t++) {
        // (A) dm[n] = max_k d[k][n]; zero z
        {
            float m = dsm[tid];
            #pragma unroll
            for (int k = 1; k < KK; k++) m = fmaxf(m, dsm[k * NN + tid]);
            dmsm[tid] = m;
        }
        for (int i = tid; i < KK * 66; i += THREADS) zsm[i] = 0.0f;
        __syncthreads();
        // (B) tk[k][n] = (d - dm) * log2(e)
        #pragma unroll
        for (int i = 0; i < KK; i++) {
            int idx = i * NN + tid;
            tsm[idx] = (dsm[idx] - dmsm[tid]) * L2E;
        }
        __syncthreads();

        // (C) z-accumulate over n: warp owns 32 n rows, lane owns o-pair
        float za[16];
        #pragma unroll
        for (int i = 0; i < 16; i++) za[i] = 0.0f;

        const int nbase = warp * 32;
        #pragma unroll 1
        for (int i = 0; i < 32; i++) {
            const int n = nbase + i;
            const float2* cp = (const float2*)(cc + ccb + (size_t)n * OO + o2);
            float2 c[KK];
            #pragma unroll
            for (int k = 0; k < KK; k++) c[k] = cp[k * (NN * OO / 2)];
            float dx = 0.0f, dy = 0.0f;
            #pragma unroll
            for (int k = 0; k < KK; k++) {
                float tk = tsm[k * NN + n];
                c[k].x = ex2(fmaf(c[k].x, L2E, tk));
                c[k].y = ex2(fmaf(c[k].y, L2E, tk));
                dx += c[k].x; dy += c[k].y;
            }
            float2 pf = __half22float2(psm[n * 33 + lane]);
            float wx = __fdividef(pf.x, dx);
            float wy = __fdividef(pf.y, dy);
            #pragma unroll
            for (int k = 0; k < KK; k++) {
                za[2 * k]     = fmaf(c[k].x, wx, za[2 * k]);
                za[2 * k + 1] = fmaf(c[k].y, wy, za[2 * k + 1]);
            }
        }
        #pragma unroll
        for (int k = 0; k < KK; k++) {
            atomicAdd(&zsm[k * 66 + o2],     za[2 * k]);
            atomicAdd(&zsm[k * 66 + o2 + 1], za[2 * k + 1]);
        }
        __syncthreads();

        // (D) squash: warps 0..7, one per k
        if (warp < KK) {
            const int k = warp;
            float z0 = zsm[k * 66 + lane];
            float z1 = zsm[k * 66 + lane + 32];
            float sq = z0 * z0 + z1 * z1;
            #pragma unroll
            for (int off = 16; off > 0; off >>= 1)
                sq += __shfl_xor_sync(0xffffffffu, sq, off);
            float cs = sq / ((1.0f + sq) * sqrtf(sq + 1e-9f));
            if (t == 2) {
                float* ob = out + ((size_t)b * KK + k) * OO;
                ob[lane]      = cs * z0;
                ob[lane + 32] = cs * z1;
            } else {
                vsm[k * 66 + lane]      = cs * z0;
                vsm[k * 66 + lane + 32] = cs * z1;
            }
        }
        if (t == 2) break;
        __syncthreads();

        // (E) sim: thread tid == n;  d[k][n] += sum_o p[n][o]*v[k][o]
        {
            float acc[KK];
            #pragma unroll
            for (int k = 0; k < KK; k++) acc[k] = 0.0f;
            #pragma unroll 4
            for (int o2i = 0; o2i < OO / 2; o2i++) {
                float2 pf = __half22float2(psm[tid * 33 + o2i]);
                #pragma unroll
                for (int k = 0; k < KK; k++) {
                    float2 vv = *(const float2*)(vsm + k * 66 + 2 * o2i);
                    acc[k] = fmaf(pf.x, vv.x, fmaf(pf.y, vv.y, acc[k]));
                }
            }
            #pragma unroll
            for (int k = 0; k < KK; k++) dsm[k * NN + tid] += acc[k];
        }
        __syncthreads();
    }
}

extern "C" void kernel_launch(void* const* d_in, const int* in_sizes, int n_in,
                              void* d_out, int out_size)
{
    const float* emb = nullptr;
    const float* S   = nullptr;
    const float* cc  = nullptr;
    for (int i = 0; i < n_in; i++) {
        if (in_sizes[i] == BB * NN * EE)           emb = (const float*)d_in[i];
        else if (in_sizes[i] == EE * OO)           S   = (const float*)d_in[i];
        else if (in_sizes[i] == BB * KK * NN * OO) cc  = (const float*)d_in[i];
    }
    float* out = (float*)d_out;

    cudaFuncSetAttribute(routing_kernel,
                         cudaFuncAttributeMaxDynamicSharedMemorySize, SMEM_BYTES);
    routing_kernel<<<BB, THREADS, SMEM_BYTES>>>(emb, S, cc, out);
}